// round 10
// baseline (speedup 1.0000x reference)
#include <cuda_runtime.h>
#include <cuda_bf16.h>
#include <cstdint>

// ---------------------------------------------------------------------------
// SudokuPasses: 4 passes of {filter(box), pointing(h), pointing(v),
// unique(h), unique(v), unique(box), doubles(v), doubles(v), doubles(box)}
// over B=32768 puzzles of (9 digits, 9 rows, 9 cols) {0,1} float masks.
//
// pack floats -> 81 x 9-bit cell masks, solve in registers (1 thread/puzzle),
// unpack to float.
// R9: doubles pair-loop flag+pd fused into ONE accumulator word
//     (flag in bits 16.., pattern union in bits 0..8) -> one predicated
//     LOP3 per pair instead of two. Profiling pad moved to the FRONT
//     (2 noops) so ncu "-s 5" lands on solve_kernel (measured +2 offset).
// ---------------------------------------------------------------------------

#define MAX_B 32768
#define CELLS 81

__device__ unsigned int g_pack[MAX_B * CELLS];

// ---------------------------------------------------------------------------
__global__ void pack_kernel(const float* __restrict__ in, int B)
{
    int idx = blockIdx.x * blockDim.x + threadIdx.x;
    if (idx >= B * CELLS) return;
    int b    = idx / CELLS;
    int cell = idx % CELLS;
    const float* p = in + (size_t)b * 729 + cell;
    unsigned m = 0;
#pragma unroll
    for (int d = 0; d < 9; ++d) {
        m |= (__ldcs(p + d * 81) != 0.0f) ? (1u << d) : 0u;
    }
    g_pack[idx] = m;
}

// ---------------------------------------------------------------------------
__global__ void unpack_kernel(float* __restrict__ out, int B)
{
    int idx = blockIdx.x * blockDim.x + threadIdx.x;
    if (idx >= B * 729) return;
    int b    = idx / 729;
    int r3   = idx % 729;
    int d    = r3 / 81;
    int cell = r3 % 81;
    unsigned m = g_pack[b * CELLS + cell];
    __stcs(out + idx, (float)((m >> d) & 1u));
}

// no-op padding: 2 at the front of each call shift ncu's "-s 5" onto
// solve_kernel (harness injects 2 launches before ours; cycle length 5:
// noop0,noop1,pack2,SOLVE3,unpack4 -> captured idx5 = position 3).
__global__ void noop_kernel() {}

// ---------------------------------------------------------------------------
#define ROW_IDX(l, k)  ((l) * 9 + (k))
#define COL_IDX(l, k)  ((k) * 9 + (l))
#define BOX_IDX(l, k)  ((((l) / 3) * 3 + ((k) / 3)) * 9 + ((l) % 3) * 3 + ((k) % 3))

// Hidden single: per-digit-bit count across the 9 cells of a line.
// count==1  <=>  parity set AND no carry ever generated.
#define UNIQUE_LINE(IDX)                                                      \
    _Pragma("unroll")                                                         \
    for (int l = 0; l < 9; ++l) {                                             \
        unsigned ones = 0, more = 0;                                          \
        _Pragma("unroll")                                                     \
        for (int k = 0; k < 9; ++k) {                                         \
            unsigned x = m[IDX(l, k)];                                        \
            more |= ones & x;                                                 \
            ones ^= x;                                                        \
        }                                                                     \
        unsigned e1 = ones & ~more;                                           \
        _Pragma("unroll")                                                     \
        for (int k = 0; k < 9; ++k) {                                         \
            unsigned v = m[IDX(l, k)];                                        \
            unsigned h = v & e1;                                              \
            m[IDX(l, k)] = h ? h : v;                                         \
        }                                                                     \
    }

// Naked pair with sentinel-guarded equality. On a match both cells hold the
// same REAL 9-bit pattern (sentinels are per-cell-unique, never match), so
// flag ((1<<c)|(1<<e), shifted to bits 16+) and the pattern union (bits 0..8)
// pack into ONE accumulator -> one predicated LOP3 per matching pair.
#define DOUBLES_LINE(IDX)                                                     \
    _Pragma("unroll")                                                         \
    for (int l = 0; l < 9; ++l) {                                             \
        unsigned v[9], qm[9];                                                 \
        _Pragma("unroll")                                                     \
        for (int k = 0; k < 9; ++k) {                                         \
            v[k]  = m[IDX(l, k)];                                             \
            qm[k] = (__popc(v[k]) == 2) ? v[k] : (0x400u << k);               \
        }                                                                     \
        unsigned acc = 0;                                                     \
        _Pragma("unroll")                                                     \
        for (int c = 0; c < 9; ++c) {                                         \
            _Pragma("unroll")                                                 \
            for (int e = c + 1; e < 9; ++e) {                                 \
                if (qm[c] == qm[e]) {                                         \
                    acc |= ((((1u << c) | (1u << e)) << 16) | qm[c]);         \
                }                                                             \
            }                                                                 \
        }                                                                     \
        unsigned flag = acc >> 16;                                            \
        unsigned npd  = ~(acc & 0x1FFu);                                      \
        _Pragma("unroll")                                                     \
        for (int k = 0; k < 9; ++k) {                                         \
            m[IDX(l, k)] = ((flag >> k) & 1u) ? v[k] : (v[k] & npd);          \
        }                                                                     \
    }

__global__ void __launch_bounds__(128)
solve_kernel(float* __restrict__ out_tail, int B, int tail_mode)
{
    int b = blockIdx.x * blockDim.x + threadIdx.x;
    if (b >= B) return;

    unsigned m[CELLS];
#pragma unroll
    for (int i = 0; i < CELLS; ++i) m[i] = g_pack[b * CELLS + i];

#pragma unroll 1
    for (int pass = 0; pass < 4; ++pass) {
        // ---- 1. filter box: solved cell's digit removed from rest of box;
        //         a digit solved twice in a box eliminates both.
#pragma unroll
        for (int bx = 0; bx < 9; ++bx) {
            const int base = (bx / 3) * 27 + (bx % 3) * 3;
            unsigned s[9], seen = 0, seen2 = 0;
#pragma unroll
            for (int k = 0; k < 9; ++k) {
                int idx = base + (k / 3) * 9 + (k % 3);
                unsigned vv = m[idx];
                unsigned sv = (__popc(vv) == 1) ? vv : 0u;
                s[k] = sv;
                seen2 |= seen & sv;
                seen  |= sv;
            }
#pragma unroll
            for (int k = 0; k < 9; ++k) {
                int idx = base + (k / 3) * 9 + (k % 3);
                unsigned other = (seen & ~s[k]) | (seen2 & s[k]);
                m[idx] &= ~other;
            }
        }

        // ---- 2. pointing h
#pragma unroll
        for (int br = 0; br < 3; ++br) {
            unsigned seg[3][3];   // [ri][bc]
#pragma unroll
            for (int ri = 0; ri < 3; ++ri)
#pragma unroll
                for (int bc = 0; bc < 3; ++bc) {
                    int c0 = (3 * br + ri) * 9 + 3 * bc;
                    seg[ri][bc] = m[c0] | m[c0 + 1] | m[c0 + 2];
                }
            unsigned p[3][3];
#pragma unroll
            for (int bc = 0; bc < 3; ++bc) {
                unsigned a = seg[0][bc], bb = seg[1][bc], cc = seg[2][bc];
                unsigned e1 = (a ^ bb ^ cc) & ~(a & bb & cc);
                p[0][bc] = a & e1;  p[1][bc] = bb & e1;  p[2][bc] = cc & e1;
            }
#pragma unroll
            for (int ri = 0; ri < 3; ++ri)
#pragma unroll
                for (int bc = 0; bc < 3; ++bc) {
                    unsigned keep = ~(p[ri][(bc + 1) % 3] | p[ri][(bc + 2) % 3]);
                    int c0 = (3 * br + ri) * 9 + 3 * bc;
                    m[c0] &= keep;  m[c0 + 1] &= keep;  m[c0 + 2] &= keep;
                }
        }

        // ---- 3. pointing v
#pragma unroll
        for (int bcol = 0; bcol < 3; ++bcol) {
            unsigned seg[3][3];   // [br][ci]
#pragma unroll
            for (int br = 0; br < 3; ++br)
#pragma unroll
                for (int ci = 0; ci < 3; ++ci) {
                    int c0 = (3 * br) * 9 + 3 * bcol + ci;
                    seg[br][ci] = m[c0] | m[c0 + 9] | m[c0 + 18];
                }
            unsigned p[3][3];
#pragma unroll
            for (int br = 0; br < 3; ++br) {
                unsigned a = seg[br][0], bb = seg[br][1], cc = seg[br][2];
                unsigned e1 = (a ^ bb ^ cc) & ~(a & bb & cc);
                p[br][0] = a & e1;  p[br][1] = bb & e1;  p[br][2] = cc & e1;
            }
#pragma unroll
            for (int br = 0; br < 3; ++br)
#pragma unroll
                for (int ci = 0; ci < 3; ++ci) {
                    unsigned keep = ~(p[(br + 1) % 3][ci] | p[(br + 2) % 3][ci]);
                    int c0 = (3 * br) * 9 + 3 * bcol + ci;
                    m[c0] &= keep;  m[c0 + 9] &= keep;  m[c0 + 18] &= keep;
                }
        }

        // ---- 4/5/6. hidden singles: rows, cols, boxes
        UNIQUE_LINE(ROW_IDX)
        UNIQUE_LINE(COL_IDX)
        UNIQUE_LINE(BOX_IDX)

        // ---- 7/8/9. naked pairs: v, v, box (reference's exact sequence)
        DOUBLES_LINE(COL_IDX)
        DOUBLES_LINE(COL_IDX)
        DOUBLES_LINE(BOX_IDX)
    }

    // write back packed result + solved flag
    bool solved = true;
#pragma unroll
    for (int i = 0; i < CELLS; ++i) {
        g_pack[b * CELLS + i] = m[i];
        solved = solved && (__popc(m[i]) == 1);
    }
    if (tail_mode == 1) {
        out_tail[b] = solved ? 1.0f : 0.0f;                 // float tail
    } else if (tail_mode == 2) {
        ((unsigned char*)out_tail)[b] = solved ? 1 : 0;     // bool-byte tail
    }
}

// ---------------------------------------------------------------------------
extern "C" void kernel_launch(void* const* d_in, const int* in_sizes, int n_in,
                              void* d_out, int out_size)
{
    const float* in = (const float*)d_in[0];
    float* out = (float*)d_out;

    int B = in_sizes[0] / 729;
    if (B > MAX_B) B = MAX_B;

    int tail_mode = 0;
    float* tail_ptr = out + (size_t)B * 729;
    if (out_size >= B * 729 + B) {
        tail_mode = 1;                                   // float-encoded bools
    } else if (out_size >= B * 729 + (B + 3) / 4) {
        tail_mode = 2;                                   // raw bool bytes
    }

    // front padding: harness emits 2 launches before ours; with these two
    // noops, overall launch #5 (ncu -s 5 -c 1) = solve_kernel below.
    noop_kernel<<<1, 1>>>();
    noop_kernel<<<1, 1>>>();

    {
        int total = B * CELLS;
        int threads = 256;
        pack_kernel<<<(total + threads - 1) / threads, threads>>>(in, B);
    }
    {
        int threads = 128;
        solve_kernel<<<(B + threads - 1) / threads, threads>>>(tail_ptr, B, tail_mode);
    }
    {
        int total = B * 729;
        int threads = 256;
        unpack_kernel<<<(total + threads - 1) / threads, threads>>>(out, B);
    }
}

// round 11
// speedup vs baseline: 1.1467x; 1.1467x over previous
#include <cuda_runtime.h>
#include <cuda_bf16.h>
#include <cstdint>

// ---------------------------------------------------------------------------
// SudokuPasses: 4 passes of {filter(box), pointing(h), pointing(v),
// unique(h), unique(v), unique(box), doubles(v), doubles(v), doubles(box)}
// over B=32768 puzzles of (9 digits, 9 rows, 9 cols) {0,1} float masks.
//
// R10: 3 threads per puzzle, each owning a COLUMN STACK (cols 3t..3t+2,
// 27 cells in registers). Boxes + columns are stack-local, so filter(box),
// pointing(v), unique(v/box) and ALL doubles stages (the op-dominant 65%)
// need no communication. Only pointing(h) (6 SHFLs) and unique(h)
// (12 SHFLs, packed 3-rows-per-word CSA partials) cross threads.
// 98304 threads (~21 warps/SM) vs 32768 -> latency-bound solver gets 3x
// the warps AND ~3x fewer ops per thread.
// ---------------------------------------------------------------------------

#define MAX_B 32768
#define CELLS 81

__device__ unsigned int g_pack[MAX_B * CELLS];

// ---------------------------------------------------------------------------
__global__ void pack_kernel(const float* __restrict__ in, int B)
{
    int idx = blockIdx.x * blockDim.x + threadIdx.x;
    if (idx >= B * CELLS) return;
    int b    = idx / CELLS;
    int cell = idx % CELLS;
    const float* p = in + (size_t)b * 729 + cell;
    unsigned m = 0;
#pragma unroll
    for (int d = 0; d < 9; ++d) {
        m |= (__ldcs(p + d * 81) != 0.0f) ? (1u << d) : 0u;
    }
    g_pack[idx] = m;
}

// ---------------------------------------------------------------------------
__global__ void unpack_kernel(float* __restrict__ out, int B)
{
    int idx = blockIdx.x * blockDim.x + threadIdx.x;
    if (idx >= B * 729) return;
    int b    = idx / 729;
    int r3   = idx % 729;
    int d    = r3 / 81;
    int cell = r3 % 81;
    unsigned m = g_pack[b * CELLS + cell];
    __stcs(out + idx, (float)((m >> d) & 1u));
}

// ---------------------------------------------------------------------------
// Stack-local line index helpers: s[] holds 27 cells, s[r*3+c] = cell
// (row r, local col c). Box br occupies s[9*br .. 9*br+8].
#define CIDX(l, k)  ((k) * 3 + (l))   // local column l, row k  (9 cells)
#define BIDX(l, k)  ((l) * 9 + (k))   // local box l, cell k    (9 cells)

// Hidden single on a local line: count==1 <=> parity & ~ever-carried.
#define UNIQUE3(IDX)                                                          \
    _Pragma("unroll")                                                         \
    for (int l = 0; l < 3; ++l) {                                             \
        unsigned ones = 0, more = 0;                                          \
        _Pragma("unroll")                                                     \
        for (int k = 0; k < 9; ++k) {                                         \
            unsigned x = s[IDX(l, k)];                                        \
            more |= ones & x;                                                 \
            ones ^= x;                                                        \
        }                                                                     \
        unsigned e1 = ones & ~more;                                           \
        _Pragma("unroll")                                                     \
        for (int k = 0; k < 9; ++k) {                                         \
            unsigned v = s[IDX(l, k)];                                        \
            unsigned h = v & e1;                                              \
            s[IDX(l, k)] = h ? h : v;                                         \
        }                                                                     \
    }

// Naked pair on a local line (sentinel-guarded equality, R8 form).
#define DOUBLES3(IDX)                                                         \
    _Pragma("unroll")                                                         \
    for (int l = 0; l < 3; ++l) {                                             \
        unsigned v[9], qm[9];                                                 \
        _Pragma("unroll")                                                     \
        for (int k = 0; k < 9; ++k) {                                         \
            v[k]  = s[IDX(l, k)];                                             \
            qm[k] = (__popc(v[k]) == 2) ? v[k] : (0x400u << k);               \
        }                                                                     \
        unsigned flag = 0, pd = 0;                                            \
        _Pragma("unroll")                                                     \
        for (int c = 0; c < 9; ++c) {                                         \
            _Pragma("unroll")                                                 \
            for (int e = c + 1; e < 9; ++e) {                                 \
                if (qm[c] == qm[e]) {                                         \
                    flag |= (1u << c) | (1u << e);                            \
                    pd   |= qm[c];                                            \
                }                                                             \
            }                                                                 \
        }                                                                     \
        unsigned npd = ~pd;                                                   \
        _Pragma("unroll")                                                     \
        for (int k = 0; k < 9; ++k) {                                         \
            s[IDX(l, k)] = ((flag >> k) & 1u) ? v[k] : (v[k] & npd);          \
        }                                                                     \
    }

__global__ void __launch_bounds__(128)
solve_kernel(float* __restrict__ out_tail, int B, int tail_mode)
{
    const int lane = threadIdx.x & 31;
    if (lane >= 30) return;                       // 10 groups of 3 per warp
    const unsigned MASK = 0x3FFFFFFFu;

    const int grp  = lane / 3;
    const int t    = lane - 3 * grp;              // stack member 0..2
    const int wid  = blockIdx.x * (blockDim.x >> 5) + (threadIdx.x >> 5);
    const int b    = wid * 10 + grp;              // puzzle index
    const int bb   = (b < B) ? b : 0;             // clamp for lockstep lanes
    const int lb   = lane - t;
    const int pl1  = lb + ((t + 1) % 3);          // partner lanes
    const int pl2  = lb + ((t + 2) % 3);

    // load my stack: global cols 3t..3t+2, all 9 rows
    unsigned s[27];
#pragma unroll
    for (int r = 0; r < 9; ++r)
#pragma unroll
        for (int c = 0; c < 3; ++c)
            s[r * 3 + c] = g_pack[bb * CELLS + r * 9 + 3 * t + c];

#pragma unroll 1
    for (int pass = 0; pass < 4; ++pass) {

        // ---- 1. filter box (3 local boxes; double-solved digits erase both)
#pragma unroll
        for (int br = 0; br < 3; ++br) {
            unsigned sv[9], seen = 0, seen2 = 0;
#pragma unroll
            for (int k = 0; k < 9; ++k) {
                unsigned vv = s[9 * br + k];
                unsigned so = (__popc(vv) == 1) ? vv : 0u;
                sv[k] = so;
                seen2 |= seen & so;
                seen  |= so;
            }
#pragma unroll
            for (int k = 0; k < 9; ++k) {
                unsigned other = (seen & ~sv[k]) | (seen2 & sv[k]);
                s[9 * br + k] &= ~other;
            }
        }

        // ---- 2. pointing h (cross-stack): digit confined to one row of my
        //        box points along that row; partners' points clear my cells.
        {
            unsigned ppk[3];
#pragma unroll
            for (int br = 0; br < 3; ++br) {
                unsigned p0 = s[9*br+0] | s[9*br+1] | s[9*br+2];
                unsigned p1 = s[9*br+3] | s[9*br+4] | s[9*br+5];
                unsigned p2 = s[9*br+6] | s[9*br+7] | s[9*br+8];
                unsigned maj = (p0 & p1) | ((p0 ^ p1) & p2);
                unsigned e1  = (p0 ^ p1 ^ p2) & ~maj;      // in exactly 1 row
                ppk[br] = (p0 & e1) | ((p1 & e1) << 9) | ((p2 & e1) << 18);
            }
#pragma unroll
            for (int br = 0; br < 3; ++br) {
                unsigned rem = __shfl_sync(MASK, ppk[br], pl1)
                             | __shfl_sync(MASK, ppk[br], pl2);
#pragma unroll
                for (int ri = 0; ri < 3; ++ri) {
                    unsigned keep = ~((rem >> (9 * ri)) & 0x1FFu);
                    s[9*br+3*ri+0] &= keep;
                    s[9*br+3*ri+1] &= keep;
                    s[9*br+3*ri+2] &= keep;
                }
            }
        }

        // ---- 3. pointing v (stack-local): digit confined to one column of a
        //        box clears that column in the other boxes of the stack.
        {
            unsigned pt[3][3];
#pragma unroll
            for (int br = 0; br < 3; ++br) {
                unsigned q0 = s[9*br+0] | s[9*br+3] | s[9*br+6];
                unsigned q1 = s[9*br+1] | s[9*br+4] | s[9*br+7];
                unsigned q2 = s[9*br+2] | s[9*br+5] | s[9*br+8];
                unsigned maj = (q0 & q1) | ((q0 ^ q1) & q2);
                unsigned e1  = (q0 ^ q1 ^ q2) & ~maj;
                pt[br][0] = q0 & e1;  pt[br][1] = q1 & e1;  pt[br][2] = q2 & e1;
            }
#pragma unroll
            for (int br = 0; br < 3; ++br)
#pragma unroll
                for (int ci = 0; ci < 3; ++ci) {
                    unsigned keep = ~(pt[(br+1)%3][ci] | pt[(br+2)%3][ci]);
                    s[9*br+ci]   &= keep;
                    s[9*br+3+ci] &= keep;
                    s[9*br+6+ci] &= keep;
                }
        }

        // ---- 4. unique h (rows, cross-stack): packed CSA partials
        //        (parity, >=2-carry) for 3 rows per word; symmetric combine.
#pragma unroll
        for (int q = 0; q < 3; ++q) {
            unsigned opk = 0, mpk = 0;
#pragma unroll
            for (int j = 0; j < 3; ++j) {
                int r = 3 * q + j;
                unsigned x0 = s[3*r], x1 = s[3*r+1], x2 = s[3*r+2];
                unsigned o  = x0 ^ x1 ^ x2;
                unsigned mm = (x0 & x1) | ((x0 ^ x1) & x2);   // >=2 of 3
                opk |= o  << (9 * j);
                mpk |= mm << (9 * j);
            }
            unsigned o1 = __shfl_sync(MASK, opk, pl1);
            unsigned o2 = __shfl_sync(MASK, opk, pl2);
            unsigned m1 = __shfl_sync(MASK, mpk, pl1);
            unsigned m2 = __shfl_sync(MASK, mpk, pl2);
            unsigned ones = opk ^ o1 ^ o2;
            unsigned more = mpk | m1 | m2 | (opk & o1) | ((opk ^ o1) & o2);
            unsigned e1p  = ones & ~more;
#pragma unroll
            for (int j = 0; j < 3; ++j) {
                int r = 3 * q + j;
                unsigned e1 = (e1p >> (9 * j)) & 0x1FFu;
#pragma unroll
                for (int c = 0; c < 3; ++c) {
                    unsigned v = s[3*r+c];
                    unsigned h = v & e1;
                    s[3*r+c] = h ? h : v;
                }
            }
        }

        // ---- 5. unique v (local cols), 6. unique box (local)
        UNIQUE3(CIDX)
        UNIQUE3(BIDX)

        // ---- 7/8/9. naked pairs: col, col, box (reference's sequence; all local)
        DOUBLES3(CIDX)
        DOUBLES3(CIDX)
        DOUBLES3(BIDX)
    }

    // solved flag: my 27 cells all one-hot, AND across the 3 stacks
    unsigned sv = 1;
#pragma unroll
    for (int i = 0; i < 27; ++i)
        sv &= (unsigned)(__popc(s[i]) == 1);
    unsigned sv1 = __shfl_sync(MASK, sv, pl1);
    unsigned sv2 = __shfl_sync(MASK, sv, pl2);
    unsigned solved = sv & sv1 & sv2;

    if (b < B) {
#pragma unroll
        for (int r = 0; r < 9; ++r)
#pragma unroll
            for (int c = 0; c < 3; ++c)
                g_pack[b * CELLS + r * 9 + 3 * t + c] = s[r * 3 + c];

        if (t == 0) {
            if (tail_mode == 1) {
                out_tail[b] = solved ? 1.0f : 0.0f;              // float tail
            } else if (tail_mode == 2) {
                ((unsigned char*)out_tail)[b] = solved ? 1 : 0;  // byte tail
            }
        }
    }
}

// ---------------------------------------------------------------------------
extern "C" void kernel_launch(void* const* d_in, const int* in_sizes, int n_in,
                              void* d_out, int out_size)
{
    const float* in = (const float*)d_in[0];
    float* out = (float*)d_out;

    int B = in_sizes[0] / 729;
    if (B > MAX_B) B = MAX_B;

    int tail_mode = 0;
    float* tail_ptr = out + (size_t)B * 729;
    if (out_size >= B * 729 + B) {
        tail_mode = 1;                                   // float-encoded bools
    } else if (out_size >= B * 729 + (B + 3) / 4) {
        tail_mode = 2;                                   // raw bool bytes
    }

    {
        int total = B * CELLS;
        int threads = 256;
        pack_kernel<<<(total + threads - 1) / threads, threads>>>(in, B);
    }
    {
        // 128 threads = 4 warps x 10 puzzles (3 lanes each, 2 idle) = 40/block
        int blocks = (B + 39) / 40;
        solve_kernel<<<blocks, 128>>>(tail_ptr, B, tail_mode);
    }
    {
        int total = B * 729;
        int threads = 256;
        unpack_kernel<<<(total + threads - 1) / threads, threads>>>(out, B);
    }
}

// round 12
// speedup vs baseline: 1.5884x; 1.3852x over previous
#include <cuda_runtime.h>
#include <cuda_bf16.h>
#include <cstdint>

// ---------------------------------------------------------------------------
// SudokuPasses: 4 passes of {filter(box), pointing(h), pointing(v),
// unique(h), unique(v), unique(box), doubles(v), doubles(v), doubles(box)}
// over B=32768 puzzles of (9 digits, 9 rows, 9 cols) {0,1} float masks.
//
// R11: ONE fused kernel. Each 128-thread block owns 40 puzzles:
//   pack (coalesced float reads -> 9-bit masks in SMEM)
//   solve (R10 register solver: 3 threads/puzzle, one column-stack each,
//          cross-stack pointing(h)/unique(h) via SHFL)
//   unpack (SMEM -> coalesced float writes)
// ~5 resident blocks/SM interleave DRAM-bound pack/unpack with ALU-bound
// solve organically; kills the g_pack round-trip (21MB) + 2 launches.
// ---------------------------------------------------------------------------

#define MAX_B 32768
#define CELLS 81
#define TPB   128          // 4 warps x 10 puzzle-groups (3 lanes each)
#define PPB   40           // puzzles per block

// Stack-local line index helpers: s[] holds 27 cells, s[r*3+c].
#define CIDX(l, k)  ((k) * 3 + (l))   // local column l, row k
#define BIDX(l, k)  ((l) * 9 + (k))   // local box l, cell k

#define UNIQUE3(IDX)                                                          \
    _Pragma("unroll")                                                         \
    for (int l = 0; l < 3; ++l) {                                             \
        unsigned ones = 0, more = 0;                                          \
        _Pragma("unroll")                                                     \
        for (int k = 0; k < 9; ++k) {                                         \
            unsigned x = s[IDX(l, k)];                                        \
            more |= ones & x;                                                 \
            ones ^= x;                                                        \
        }                                                                     \
        unsigned e1 = ones & ~more;                                           \
        _Pragma("unroll")                                                     \
        for (int k = 0; k < 9; ++k) {                                         \
            unsigned v = s[IDX(l, k)];                                        \
            unsigned h = v & e1;                                              \
            s[IDX(l, k)] = h ? h : v;                                         \
        }                                                                     \
    }

#define DOUBLES3(IDX)                                                         \
    _Pragma("unroll")                                                         \
    for (int l = 0; l < 3; ++l) {                                             \
        unsigned v[9], qm[9];                                                 \
        _Pragma("unroll")                                                     \
        for (int k = 0; k < 9; ++k) {                                         \
            v[k]  = s[IDX(l, k)];                                             \
            qm[k] = (__popc(v[k]) == 2) ? v[k] : (0x400u << k);               \
        }                                                                     \
        unsigned flag = 0, pd = 0;                                            \
        _Pragma("unroll")                                                     \
        for (int c = 0; c < 9; ++c) {                                         \
            _Pragma("unroll")                                                 \
            for (int e = c + 1; e < 9; ++e) {                                 \
                if (qm[c] == qm[e]) {                                         \
                    flag |= (1u << c) | (1u << e);                            \
                    pd   |= qm[c];                                            \
                }                                                             \
            }                                                                 \
        }                                                                     \
        unsigned npd = ~pd;                                                   \
        _Pragma("unroll")                                                     \
        for (int k = 0; k < 9; ++k) {                                         \
            s[IDX(l, k)] = ((flag >> k) & 1u) ? v[k] : (v[k] & npd);          \
        }                                                                     \
    }

__global__ void __launch_bounds__(TPB, 5)
fused_kernel(const float* __restrict__ in, float* __restrict__ out,
             float* __restrict__ out_tail, int B, int tail_mode)
{
    __shared__ unsigned sm[PPB * CELLS];      // 12.96 KB

    const int tid   = threadIdx.x;
    const int baseP = blockIdx.x * PPB;
    const int nP    = (B - baseP < PPB) ? (B - baseP) : PPB;

    // ================= pack phase (coalesced reads) =================
    for (int w = tid; w < nP * CELLS; w += TPB) {
        int p    = w / CELLS;
        int cell = w - p * CELLS;
        const float* q = in + (size_t)(baseP + p) * 729 + cell;
        unsigned mm = 0;
#pragma unroll
        for (int d = 0; d < 9; ++d)
            mm |= (__ldcs(q + d * 81) != 0.0f) ? (1u << d) : 0u;
        sm[w] = mm;
    }
    __syncthreads();

    // ================= solve phase (R10 solver, smem-backed) =================
    const int lane = tid & 31;
    if (lane < 30) {
        const unsigned MASK = 0x3FFFFFFFu;
        const int grp  = lane / 3;
        const int t    = lane - 3 * grp;
        const int ploc = (tid >> 5) * 10 + grp;       // 0..39
        const int b    = baseP + ploc;
        const bool valid = (b < B);
        const int lb   = lane - t;
        const int pl1  = lb + ((t + 1) % 3);
        const int pl2  = lb + ((t + 2) % 3);

        unsigned s[27];
#pragma unroll
        for (int r = 0; r < 9; ++r)
#pragma unroll
            for (int c = 0; c < 3; ++c)
                s[r * 3 + c] = sm[ploc * CELLS + r * 9 + 3 * t + c];

#pragma unroll 1
        for (int pass = 0; pass < 4; ++pass) {

            // ---- 1. filter box (3 local boxes)
#pragma unroll
            for (int br = 0; br < 3; ++br) {
                unsigned sv[9], seen = 0, seen2 = 0;
#pragma unroll
                for (int k = 0; k < 9; ++k) {
                    unsigned vv = s[9 * br + k];
                    unsigned so = (__popc(vv) == 1) ? vv : 0u;
                    sv[k] = so;
                    seen2 |= seen & so;
                    seen  |= so;
                }
#pragma unroll
                for (int k = 0; k < 9; ++k) {
                    unsigned other = (seen & ~sv[k]) | (seen2 & sv[k]);
                    s[9 * br + k] &= ~other;
                }
            }

            // ---- 2. pointing h (cross-stack via SHFL)
            {
                unsigned ppk[3];
#pragma unroll
                for (int br = 0; br < 3; ++br) {
                    unsigned p0 = s[9*br+0] | s[9*br+1] | s[9*br+2];
                    unsigned p1 = s[9*br+3] | s[9*br+4] | s[9*br+5];
                    unsigned p2 = s[9*br+6] | s[9*br+7] | s[9*br+8];
                    unsigned maj = (p0 & p1) | ((p0 ^ p1) & p2);
                    unsigned e1  = (p0 ^ p1 ^ p2) & ~maj;
                    ppk[br] = (p0 & e1) | ((p1 & e1) << 9) | ((p2 & e1) << 18);
                }
#pragma unroll
                for (int br = 0; br < 3; ++br) {
                    unsigned rem = __shfl_sync(MASK, ppk[br], pl1)
                                 | __shfl_sync(MASK, ppk[br], pl2);
#pragma unroll
                    for (int ri = 0; ri < 3; ++ri) {
                        unsigned keep = ~((rem >> (9 * ri)) & 0x1FFu);
                        s[9*br+3*ri+0] &= keep;
                        s[9*br+3*ri+1] &= keep;
                        s[9*br+3*ri+2] &= keep;
                    }
                }
            }

            // ---- 3. pointing v (stack-local)
            {
                unsigned pt[3][3];
#pragma unroll
                for (int br = 0; br < 3; ++br) {
                    unsigned q0 = s[9*br+0] | s[9*br+3] | s[9*br+6];
                    unsigned q1 = s[9*br+1] | s[9*br+4] | s[9*br+7];
                    unsigned q2 = s[9*br+2] | s[9*br+5] | s[9*br+8];
                    unsigned maj = (q0 & q1) | ((q0 ^ q1) & q2);
                    unsigned e1  = (q0 ^ q1 ^ q2) & ~maj;
                    pt[br][0] = q0 & e1;  pt[br][1] = q1 & e1;  pt[br][2] = q2 & e1;
                }
#pragma unroll
                for (int br = 0; br < 3; ++br)
#pragma unroll
                    for (int ci = 0; ci < 3; ++ci) {
                        unsigned keep = ~(pt[(br+1)%3][ci] | pt[(br+2)%3][ci]);
                        s[9*br+ci]   &= keep;
                        s[9*br+3+ci] &= keep;
                        s[9*br+6+ci] &= keep;
                    }
            }

            // ---- 4. unique h (rows, cross-stack, packed CSA partials)
#pragma unroll
            for (int q = 0; q < 3; ++q) {
                unsigned opk = 0, mpk = 0;
#pragma unroll
                for (int j = 0; j < 3; ++j) {
                    int r = 3 * q + j;
                    unsigned x0 = s[3*r], x1 = s[3*r+1], x2 = s[3*r+2];
                    unsigned o  = x0 ^ x1 ^ x2;
                    unsigned mm = (x0 & x1) | ((x0 ^ x1) & x2);
                    opk |= o  << (9 * j);
                    mpk |= mm << (9 * j);
                }
                unsigned o1 = __shfl_sync(MASK, opk, pl1);
                unsigned o2 = __shfl_sync(MASK, opk, pl2);
                unsigned m1 = __shfl_sync(MASK, mpk, pl1);
                unsigned m2 = __shfl_sync(MASK, mpk, pl2);
                unsigned ones = opk ^ o1 ^ o2;
                unsigned more = mpk | m1 | m2 | (opk & o1) | ((opk ^ o1) & o2);
                unsigned e1p  = ones & ~more;
#pragma unroll
                for (int j = 0; j < 3; ++j) {
                    int r = 3 * q + j;
                    unsigned e1 = (e1p >> (9 * j)) & 0x1FFu;
#pragma unroll
                    for (int c = 0; c < 3; ++c) {
                        unsigned v = s[3*r+c];
                        unsigned h = v & e1;
                        s[3*r+c] = h ? h : v;
                    }
                }
            }

            // ---- 5/6. unique v (local cols), unique box (local)
            UNIQUE3(CIDX)
            UNIQUE3(BIDX)

            // ---- 7/8/9. naked pairs: col, col, box
            DOUBLES3(CIDX)
            DOUBLES3(CIDX)
            DOUBLES3(BIDX)
        }

        // solved flag across the 3 stacks
        unsigned svf = 1;
#pragma unroll
        for (int i = 0; i < 27; ++i)
            svf &= (unsigned)(__popc(s[i]) == 1);
        unsigned sv1 = __shfl_sync(MASK, svf, pl1);
        unsigned sv2 = __shfl_sync(MASK, svf, pl2);
        unsigned solved = svf & sv1 & sv2;

        if (valid) {
#pragma unroll
            for (int r = 0; r < 9; ++r)
#pragma unroll
                for (int c = 0; c < 3; ++c)
                    sm[ploc * CELLS + r * 9 + 3 * t + c] = s[r * 3 + c];

            if (t == 0) {
                if (tail_mode == 1) {
                    out_tail[b] = solved ? 1.0f : 0.0f;
                } else if (tail_mode == 2) {
                    ((unsigned char*)out_tail)[b] = solved ? 1 : 0;
                }
            }
        }
    }
    __syncthreads();

    // ================= unpack phase (coalesced writes) =================
    const size_t baseF = (size_t)baseP * 729;
    for (int i = tid; i < nP * 729; i += TPB) {
        int p    = i / 729;
        int r3   = i - p * 729;
        int d    = r3 / 81;
        int cell = r3 - d * 81;
        __stcs(out + baseF + i, (float)((sm[p * CELLS + cell] >> d) & 1u));
    }
}

// ---------------------------------------------------------------------------
extern "C" void kernel_launch(void* const* d_in, const int* in_sizes, int n_in,
                              void* d_out, int out_size)
{
    const float* in = (const float*)d_in[0];
    float* out = (float*)d_out;

    int B = in_sizes[0] / 729;
    if (B > MAX_B) B = MAX_B;

    int tail_mode = 0;
    float* tail_ptr = out + (size_t)B * 729;
    if (out_size >= B * 729 + B) {
        tail_mode = 1;                                   // float-encoded bools
    } else if (out_size >= B * 729 + (B + 3) / 4) {
        tail_mode = 2;                                   // raw bool bytes
    }

    int blocks = (B + PPB - 1) / PPB;
    fused_kernel<<<blocks, TPB>>>(in, out, tail_ptr, B, tail_mode);
}

// round 13
// speedup vs baseline: 1.5906x; 1.0014x over previous
#include <cuda_runtime.h>
#include <cuda_bf16.h>
#include <cstdint>

// ---------------------------------------------------------------------------
// SudokuPasses: 4 passes of {filter(box), pointing(h), pointing(v),
// unique(h), unique(v), unique(box), doubles(v), doubles(v), doubles(box)}
// over B=32768 puzzles of (9 digits, 9 rows, 9 cols) {0,1} float masks.
//
// R12: R11 fused kernel (pack->solve->unpack via SMEM, 3 threads/puzzle
// column-stack solver) with __launch_bounds__(128, 6):
//   * 6 resident blocks/SM (regs=80 fits: 6*128*80 = 61440 <= 64K)
//   * capacity 148*6 = 888 blocks >= grid 820 -> the WHOLE grid is one
//     wave (was 1.11 waves with a low-occupancy 80-block straggler)
//   * +2 warps/SM of latency hiding for the issue=50% solver
// ---------------------------------------------------------------------------

#define MAX_B 32768
#define CELLS 81
#define TPB   128          // 4 warps x 10 puzzle-groups (3 lanes each)
#define PPB   40           // puzzles per block

// Stack-local line index helpers: s[] holds 27 cells, s[r*3+c].
#define CIDX(l, k)  ((k) * 3 + (l))   // local column l, row k
#define BIDX(l, k)  ((l) * 9 + (k))   // local box l, cell k

#define UNIQUE3(IDX)                                                          \
    _Pragma("unroll")                                                         \
    for (int l = 0; l < 3; ++l) {                                             \
        unsigned ones = 0, more = 0;                                          \
        _Pragma("unroll")                                                     \
        for (int k = 0; k < 9; ++k) {                                         \
            unsigned x = s[IDX(l, k)];                                        \
            more |= ones & x;                                                 \
            ones ^= x;                                                        \
        }                                                                     \
        unsigned e1 = ones & ~more;                                           \
        _Pragma("unroll")                                                     \
        for (int k = 0; k < 9; ++k) {                                         \
            unsigned v = s[IDX(l, k)];                                        \
            unsigned h = v & e1;                                              \
            s[IDX(l, k)] = h ? h : v;                                         \
        }                                                                     \
    }

#define DOUBLES3(IDX)                                                         \
    _Pragma("unroll")                                                         \
    for (int l = 0; l < 3; ++l) {                                             \
        unsigned v[9], qm[9];                                                 \
        _Pragma("unroll")                                                     \
        for (int k = 0; k < 9; ++k) {                                         \
            v[k]  = s[IDX(l, k)];                                             \
            qm[k] = (__popc(v[k]) == 2) ? v[k] : (0x400u << k);               \
        }                                                                     \
        unsigned flag = 0, pd = 0;                                            \
        _Pragma("unroll")                                                     \
        for (int c = 0; c < 9; ++c) {                                         \
            _Pragma("unroll")                                                 \
            for (int e = c + 1; e < 9; ++e) {                                 \
                if (qm[c] == qm[e]) {                                         \
                    flag |= (1u << c) | (1u << e);                            \
                    pd   |= qm[c];                                            \
                }                                                             \
            }                                                                 \
        }                                                                     \
        unsigned npd = ~pd;                                                   \
        _Pragma("unroll")                                                     \
        for (int k = 0; k < 9; ++k) {                                         \
            s[IDX(l, k)] = ((flag >> k) & 1u) ? v[k] : (v[k] & npd);          \
        }                                                                     \
    }

__global__ void __launch_bounds__(TPB, 6)
fused_kernel(const float* __restrict__ in, float* __restrict__ out,
             float* __restrict__ out_tail, int B, int tail_mode)
{
    __shared__ unsigned sm[PPB * CELLS];      // 12.96 KB

    const int tid   = threadIdx.x;
    const int baseP = blockIdx.x * PPB;
    const int nP    = (B - baseP < PPB) ? (B - baseP) : PPB;

    // ================= pack phase (coalesced reads) =================
    for (int w = tid; w < nP * CELLS; w += TPB) {
        int p    = w / CELLS;
        int cell = w - p * CELLS;
        const float* q = in + (size_t)(baseP + p) * 729 + cell;
        unsigned mm = 0;
#pragma unroll
        for (int d = 0; d < 9; ++d)
            mm |= (__ldcs(q + d * 81) != 0.0f) ? (1u << d) : 0u;
        sm[w] = mm;
    }
    __syncthreads();

    // ================= solve phase (register solver, smem-backed) ==========
    const int lane = tid & 31;
    if (lane < 30) {
        const unsigned MASK = 0x3FFFFFFFu;
        const int grp  = lane / 3;
        const int t    = lane - 3 * grp;
        const int ploc = (tid >> 5) * 10 + grp;       // 0..39
        const int b    = baseP + ploc;
        const bool valid = (b < B);
        const int lb   = lane - t;
        const int pl1  = lb + ((t + 1) % 3);
        const int pl2  = lb + ((t + 2) % 3);

        unsigned s[27];
#pragma unroll
        for (int r = 0; r < 9; ++r)
#pragma unroll
            for (int c = 0; c < 3; ++c)
                s[r * 3 + c] = sm[ploc * CELLS + r * 9 + 3 * t + c];

#pragma unroll 1
        for (int pass = 0; pass < 4; ++pass) {

            // ---- 1. filter box (3 local boxes)
#pragma unroll
            for (int br = 0; br < 3; ++br) {
                unsigned sv[9], seen = 0, seen2 = 0;
#pragma unroll
                for (int k = 0; k < 9; ++k) {
                    unsigned vv = s[9 * br + k];
                    unsigned so = (__popc(vv) == 1) ? vv : 0u;
                    sv[k] = so;
                    seen2 |= seen & so;
                    seen  |= so;
                }
#pragma unroll
                for (int k = 0; k < 9; ++k) {
                    unsigned other = (seen & ~sv[k]) | (seen2 & sv[k]);
                    s[9 * br + k] &= ~other;
                }
            }

            // ---- 2. pointing h (cross-stack via SHFL)
            {
                unsigned ppk[3];
#pragma unroll
                for (int br = 0; br < 3; ++br) {
                    unsigned p0 = s[9*br+0] | s[9*br+1] | s[9*br+2];
                    unsigned p1 = s[9*br+3] | s[9*br+4] | s[9*br+5];
                    unsigned p2 = s[9*br+6] | s[9*br+7] | s[9*br+8];
                    unsigned maj = (p0 & p1) | ((p0 ^ p1) & p2);
                    unsigned e1  = (p0 ^ p1 ^ p2) & ~maj;
                    ppk[br] = (p0 & e1) | ((p1 & e1) << 9) | ((p2 & e1) << 18);
                }
#pragma unroll
                for (int br = 0; br < 3; ++br) {
                    unsigned rem = __shfl_sync(MASK, ppk[br], pl1)
                                 | __shfl_sync(MASK, ppk[br], pl2);
#pragma unroll
                    for (int ri = 0; ri < 3; ++ri) {
                        unsigned keep = ~((rem >> (9 * ri)) & 0x1FFu);
                        s[9*br+3*ri+0] &= keep;
                        s[9*br+3*ri+1] &= keep;
                        s[9*br+3*ri+2] &= keep;
                    }
                }
            }

            // ---- 3. pointing v (stack-local)
            {
                unsigned pt[3][3];
#pragma unroll
                for (int br = 0; br < 3; ++br) {
                    unsigned q0 = s[9*br+0] | s[9*br+3] | s[9*br+6];
                    unsigned q1 = s[9*br+1] | s[9*br+4] | s[9*br+7];
                    unsigned q2 = s[9*br+2] | s[9*br+5] | s[9*br+8];
                    unsigned maj = (q0 & q1) | ((q0 ^ q1) & q2);
                    unsigned e1  = (q0 ^ q1 ^ q2) & ~maj;
                    pt[br][0] = q0 & e1;  pt[br][1] = q1 & e1;  pt[br][2] = q2 & e1;
                }
#pragma unroll
                for (int br = 0; br < 3; ++br)
#pragma unroll
                    for (int ci = 0; ci < 3; ++ci) {
                        unsigned keep = ~(pt[(br+1)%3][ci] | pt[(br+2)%3][ci]);
                        s[9*br+ci]   &= keep;
                        s[9*br+3+ci] &= keep;
                        s[9*br+6+ci] &= keep;
                    }
            }

            // ---- 4. unique h (rows, cross-stack, packed CSA partials)
#pragma unroll
            for (int q = 0; q < 3; ++q) {
                unsigned opk = 0, mpk = 0;
#pragma unroll
                for (int j = 0; j < 3; ++j) {
                    int r = 3 * q + j;
                    unsigned x0 = s[3*r], x1 = s[3*r+1], x2 = s[3*r+2];
                    unsigned o  = x0 ^ x1 ^ x2;
                    unsigned mm = (x0 & x1) | ((x0 ^ x1) & x2);
                    opk |= o  << (9 * j);
                    mpk |= mm << (9 * j);
                }
                unsigned o1 = __shfl_sync(MASK, opk, pl1);
                unsigned o2 = __shfl_sync(MASK, opk, pl2);
                unsigned m1 = __shfl_sync(MASK, mpk, pl1);
                unsigned m2 = __shfl_sync(MASK, mpk, pl2);
                unsigned ones = opk ^ o1 ^ o2;
                unsigned more = mpk | m1 | m2 | (opk & o1) | ((opk ^ o1) & o2);
                unsigned e1p  = ones & ~more;
#pragma unroll
                for (int j = 0; j < 3; ++j) {
                    int r = 3 * q + j;
                    unsigned e1 = (e1p >> (9 * j)) & 0x1FFu;
#pragma unroll
                    for (int c = 0; c < 3; ++c) {
                        unsigned v = s[3*r+c];
                        unsigned h = v & e1;
                        s[3*r+c] = h ? h : v;
                    }
                }
            }

            // ---- 5/6. unique v (local cols), unique box (local)
            UNIQUE3(CIDX)
            UNIQUE3(BIDX)

            // ---- 7/8/9. naked pairs: col, col, box
            DOUBLES3(CIDX)
            DOUBLES3(CIDX)
            DOUBLES3(BIDX)
        }

        // solved flag across the 3 stacks
        unsigned svf = 1;
#pragma unroll
        for (int i = 0; i < 27; ++i)
            svf &= (unsigned)(__popc(s[i]) == 1);
        unsigned sv1 = __shfl_sync(MASK, svf, pl1);
        unsigned sv2 = __shfl_sync(MASK, svf, pl2);
        unsigned solved = svf & sv1 & sv2;

        if (valid) {
#pragma unroll
            for (int r = 0; r < 9; ++r)
#pragma unroll
                for (int c = 0; c < 3; ++c)
                    sm[ploc * CELLS + r * 9 + 3 * t + c] = s[r * 3 + c];

            if (t == 0) {
                if (tail_mode == 1) {
                    out_tail[b] = solved ? 1.0f : 0.0f;
                } else if (tail_mode == 2) {
                    ((unsigned char*)out_tail)[b] = solved ? 1 : 0;
                }
            }
        }
    }
    __syncthreads();

    // ================= unpack phase (coalesced writes) =================
    const size_t baseF = (size_t)baseP * 729;
    for (int i = tid; i < nP * 729; i += TPB) {
        int p    = i / 729;
        int r3   = i - p * 729;
        int d    = r3 / 81;
        int cell = r3 - d * 81;
        __stcs(out + baseF + i, (float)((sm[p * CELLS + cell] >> d) & 1u));
    }
}

// ---------------------------------------------------------------------------
extern "C" void kernel_launch(void* const* d_in, const int* in_sizes, int n_in,
                              void* d_out, int out_size)
{
    const float* in = (const float*)d_in[0];
    float* out = (float*)d_out;

    int B = in_sizes[0] / 729;
    if (B > MAX_B) B = MAX_B;

    int tail_mode = 0;
    float* tail_ptr = out + (size_t)B * 729;
    if (out_size >= B * 729 + B) {
        tail_mode = 1;                                   // float-encoded bools
    } else if (out_size >= B * 729 + (B + 3) / 4) {
        tail_mode = 2;                                   // raw bool bytes
    }

    int blocks = (B + PPB - 1) / PPB;   // 820 for B=32768; fits one wave @6/SM
    fused_kernel<<<blocks, TPB>>>(in, out, tail_ptr, B, tail_mode);
}

// round 14
// speedup vs baseline: 1.7481x; 1.0990x over previous
#include <cuda_runtime.h>
#include <cuda_bf16.h>
#include <cstdint>

// ---------------------------------------------------------------------------
// SudokuPasses: 4 passes of {filter(box), pointing(h), pointing(v),
// unique(h), unique(v), unique(box), doubles(v), doubles(v), doubles(box)}
// over B=32768 puzzles of (9 digits, 9 rows, 9 cols) {0,1} float masks.
//
// R13: warp-autonomous fused kernel. Each WARP owns 10 puzzles and a private
// 810-word smem segment: pack -> solve (3 lanes/puzzle column-stack solver)
// -> unpack, with only __syncwarp() between phases. No block barriers ->
// warps drift out of phase, overlapping DRAM-bound pack/unpack with the
// alu-bound solve. Pack/unpack loops are division-free (register counters,
// 128B-coalesced) and bit->float uses IMAD (fma pipe) instead of I2F.
// ---------------------------------------------------------------------------

#define MAX_B 32768
#define CELLS 81
#define TPB   128        // 4 warps x 10 puzzles each
#define PPW   10         // puzzles per warp
#define PPB   (PPW * (TPB / 32))   // 40 puzzles per block

// Stack-local line index helpers: s[] holds 27 cells, s[r*3+c].
#define CIDX(l, k)  ((k) * 3 + (l))   // local column l, row k
#define BIDX(l, k)  ((l) * 9 + (k))   // local box l, cell k

#define UNIQUE3(IDX)                                                          \
    _Pragma("unroll")                                                         \
    for (int l = 0; l < 3; ++l) {                                             \
        unsigned ones = 0, more = 0;                                          \
        _Pragma("unroll")                                                     \
        for (int k = 0; k < 9; ++k) {                                         \
            unsigned x = s[IDX(l, k)];                                        \
            more |= ones & x;                                                 \
            ones ^= x;                                                        \
        }                                                                     \
        unsigned e1 = ones & ~more;                                           \
        _Pragma("unroll")                                                     \
        for (int k = 0; k < 9; ++k) {                                         \
            unsigned v = s[IDX(l, k)];                                        \
            unsigned h = v & e1;                                              \
            s[IDX(l, k)] = h ? h : v;                                         \
        }                                                                     \
    }

#define DOUBLES3(IDX)                                                         \
    _Pragma("unroll")                                                         \
    for (int l = 0; l < 3; ++l) {                                             \
        unsigned v[9], qm[9];                                                 \
        _Pragma("unroll")                                                     \
        for (int k = 0; k < 9; ++k) {                                         \
            v[k]  = s[IDX(l, k)];                                             \
            qm[k] = (__popc(v[k]) == 2) ? v[k] : (0x400u << k);               \
        }                                                                     \
        unsigned flag = 0, pd = 0;                                            \
        _Pragma("unroll")                                                     \
        for (int c = 0; c < 9; ++c) {                                         \
            _Pragma("unroll")                                                 \
            for (int e = c + 1; e < 9; ++e) {                                 \
                if (qm[c] == qm[e]) {                                         \
                    flag |= (1u << c) | (1u << e);                            \
                    pd   |= qm[c];                                            \
                }                                                             \
            }                                                                 \
        }                                                                     \
        unsigned npd = ~pd;                                                   \
        _Pragma("unroll")                                                     \
        for (int k = 0; k < 9; ++k) {                                         \
            s[IDX(l, k)] = ((flag >> k) & 1u) ? v[k] : (v[k] & npd);          \
        }                                                                     \
    }

__global__ void __launch_bounds__(TPB, 6)
fused_kernel(const float* __restrict__ in, float* __restrict__ out,
             float* __restrict__ out_tail, int B, int tail_mode)
{
    __shared__ unsigned sm[PPB * CELLS];          // 12.96 KB, per-warp segments

    const int tid      = threadIdx.x;
    const int lane     = tid & 31;
    const int w        = tid >> 5;
    const int warpBase = blockIdx.x * PPB + w * PPW;   // first puzzle of warp
    int nW = B - warpBase;
    if (nW > PPW) nW = PPW;
    if (nW < 0)   nW = 0;
    unsigned* seg = sm + w * (PPW * CELLS);

    // ================= pack (warp-private, division-free) =================
    for (int p = 0; p < nW; ++p) {
        const float* q = in + (size_t)(warpBase + p) * 729;
#pragma unroll
        for (int it = 0; it < 3; ++it) {
            int cell = lane + 32 * it;
            if (cell < CELLS) {
                unsigned mm = 0;
#pragma unroll
                for (int d = 0; d < 9; ++d)
                    mm |= (__ldcs(q + d * 81 + cell) != 0.0f) ? (1u << d) : 0u;
                seg[p * CELLS + cell] = mm;
            }
        }
    }
    __syncwarp();

    // ================= solve (3 lanes per puzzle, lanes 0..29) =============
    if (lane < 30) {
        const unsigned MASK = 0x3FFFFFFFu;
        const int grp  = lane / 3;                 // 0..9 = local puzzle
        const int t    = lane - 3 * grp;           // stack member 0..2
        const int b    = warpBase + grp;
        const bool valid = (grp < nW);
        const int lb   = lane - t;
        const int pl1  = lb + ((t + 1) % 3);
        const int pl2  = lb + ((t + 2) % 3);

        unsigned s[27];
#pragma unroll
        for (int r = 0; r < 9; ++r)
#pragma unroll
            for (int c = 0; c < 3; ++c)
                s[r * 3 + c] = seg[grp * CELLS + r * 9 + 3 * t + c];

#pragma unroll 1
        for (int pass = 0; pass < 4; ++pass) {

            // ---- 1. filter box (3 local boxes)
#pragma unroll
            for (int br = 0; br < 3; ++br) {
                unsigned sv[9], seen = 0, seen2 = 0;
#pragma unroll
                for (int k = 0; k < 9; ++k) {
                    unsigned vv = s[9 * br + k];
                    unsigned so = (__popc(vv) == 1) ? vv : 0u;
                    sv[k] = so;
                    seen2 |= seen & so;
                    seen  |= so;
                }
#pragma unroll
                for (int k = 0; k < 9; ++k) {
                    unsigned other = (seen & ~sv[k]) | (seen2 & sv[k]);
                    s[9 * br + k] &= ~other;
                }
            }

            // ---- 2. pointing h (cross-stack via SHFL)
            {
                unsigned ppk[3];
#pragma unroll
                for (int br = 0; br < 3; ++br) {
                    unsigned p0 = s[9*br+0] | s[9*br+1] | s[9*br+2];
                    unsigned p1 = s[9*br+3] | s[9*br+4] | s[9*br+5];
                    unsigned p2 = s[9*br+6] | s[9*br+7] | s[9*br+8];
                    unsigned maj = (p0 & p1) | ((p0 ^ p1) & p2);
                    unsigned e1  = (p0 ^ p1 ^ p2) & ~maj;
                    ppk[br] = (p0 & e1) | ((p1 & e1) << 9) | ((p2 & e1) << 18);
                }
#pragma unroll
                for (int br = 0; br < 3; ++br) {
                    unsigned rem = __shfl_sync(MASK, ppk[br], pl1)
                                 | __shfl_sync(MASK, ppk[br], pl2);
#pragma unroll
                    for (int ri = 0; ri < 3; ++ri) {
                        unsigned keep = ~((rem >> (9 * ri)) & 0x1FFu);
                        s[9*br+3*ri+0] &= keep;
                        s[9*br+3*ri+1] &= keep;
                        s[9*br+3*ri+2] &= keep;
                    }
                }
            }

            // ---- 3. pointing v (stack-local)
            {
                unsigned pt[3][3];
#pragma unroll
                for (int br = 0; br < 3; ++br) {
                    unsigned q0 = s[9*br+0] | s[9*br+3] | s[9*br+6];
                    unsigned q1 = s[9*br+1] | s[9*br+4] | s[9*br+7];
                    unsigned q2 = s[9*br+2] | s[9*br+5] | s[9*br+8];
                    unsigned maj = (q0 & q1) | ((q0 ^ q1) & q2);
                    unsigned e1  = (q0 ^ q1 ^ q2) & ~maj;
                    pt[br][0] = q0 & e1;  pt[br][1] = q1 & e1;  pt[br][2] = q2 & e1;
                }
#pragma unroll
                for (int br = 0; br < 3; ++br)
#pragma unroll
                    for (int ci = 0; ci < 3; ++ci) {
                        unsigned keep = ~(pt[(br+1)%3][ci] | pt[(br+2)%3][ci]);
                        s[9*br+ci]   &= keep;
                        s[9*br+3+ci] &= keep;
                        s[9*br+6+ci] &= keep;
                    }
            }

            // ---- 4. unique h (rows, cross-stack, packed CSA partials)
#pragma unroll
            for (int q = 0; q < 3; ++q) {
                unsigned opk = 0, mpk = 0;
#pragma unroll
                for (int j = 0; j < 3; ++j) {
                    int r = 3 * q + j;
                    unsigned x0 = s[3*r], x1 = s[3*r+1], x2 = s[3*r+2];
                    unsigned o  = x0 ^ x1 ^ x2;
                    unsigned mm = (x0 & x1) | ((x0 ^ x1) & x2);
                    opk |= o  << (9 * j);
                    mpk |= mm << (9 * j);
                }
                unsigned o1 = __shfl_sync(MASK, opk, pl1);
                unsigned o2 = __shfl_sync(MASK, opk, pl2);
                unsigned m1 = __shfl_sync(MASK, mpk, pl1);
                unsigned m2 = __shfl_sync(MASK, mpk, pl2);
                unsigned ones = opk ^ o1 ^ o2;
                unsigned more = mpk | m1 | m2 | (opk & o1) | ((opk ^ o1) & o2);
                unsigned e1p  = ones & ~more;
#pragma unroll
                for (int j = 0; j < 3; ++j) {
                    int r = 3 * q + j;
                    unsigned e1 = (e1p >> (9 * j)) & 0x1FFu;
#pragma unroll
                    for (int c = 0; c < 3; ++c) {
                        unsigned v = s[3*r+c];
                        unsigned h = v & e1;
                        s[3*r+c] = h ? h : v;
                    }
                }
            }

            // ---- 5/6. unique v (local cols), unique box (local)
            UNIQUE3(CIDX)
            UNIQUE3(BIDX)

            // ---- 7/8/9. naked pairs: col, col, box
            DOUBLES3(CIDX)
            DOUBLES3(CIDX)
            DOUBLES3(BIDX)
        }

        // solved flag across the 3 stacks
        unsigned svf = 1;
#pragma unroll
        for (int i = 0; i < 27; ++i)
            svf &= (unsigned)(__popc(s[i]) == 1);
        unsigned sv1 = __shfl_sync(MASK, svf, pl1);
        unsigned sv2 = __shfl_sync(MASK, svf, pl2);
        unsigned solved = svf & sv1 & sv2;

        if (valid) {
#pragma unroll
            for (int r = 0; r < 9; ++r)
#pragma unroll
                for (int c = 0; c < 3; ++c)
                    seg[grp * CELLS + r * 9 + 3 * t + c] = s[r * 3 + c];

            if (t == 0) {
                if (tail_mode == 1) {
                    out_tail[b] = solved ? 1.0f : 0.0f;
                } else if (tail_mode == 2) {
                    ((unsigned char*)out_tail)[b] = solved ? 1 : 0;
                }
            }
        }
    }
    __syncwarp();

    // ================= unpack (warp-private, division-free) ================
    for (int p = 0; p < nW; ++p) {
        float* q = out + (size_t)(warpBase + p) * 729;
#pragma unroll
        for (int it = 0; it < 3; ++it) {
            int cell = lane + 32 * it;
            if (cell < CELLS) {
                unsigned mm = seg[p * CELLS + cell];
#pragma unroll
                for (int d = 0; d < 9; ++d)
                    __stcs(q + d * 81 + cell,
                           __uint_as_float(((mm >> d) & 1u) * 0x3F800000u));
            }
        }
    }
}

// ---------------------------------------------------------------------------
extern "C" void kernel_launch(void* const* d_in, const int* in_sizes, int n_in,
                              void* d_out, int out_size)
{
    const float* in = (const float*)d_in[0];
    float* out = (float*)d_out;

    int B = in_sizes[0] / 729;
    if (B > MAX_B) B = MAX_B;

    int tail_mode = 0;
    float* tail_ptr = out + (size_t)B * 729;
    if (out_size >= B * 729 + B) {
        tail_mode = 1;                                   // float-encoded bools
    } else if (out_size >= B * 729 + (B + 3) / 4) {
        tail_mode = 2;                                   // raw bool bytes
    }

    int blocks = (B + PPB - 1) / PPB;   // 820 for B=32768
    fused_kernel<<<blocks, TPB>>>(in, out, tail_ptr, B, tail_mode);
}

// round 15
// speedup vs baseline: 1.8395x; 1.0523x over previous
#include <cuda_runtime.h>
#include <cuda_bf16.h>
#include <cstdint>

// ---------------------------------------------------------------------------
// SudokuPasses: 4 passes of {filter(box), pointing(h), pointing(v),
// unique(h), unique(v), unique(box), doubles(v), doubles(v), doubles(box)}
// over B=32768 puzzles of (9 digits, 9 rows, 9 cols) {0,1} float masks.
//
// R14: R13 warp-autonomous fused kernel with __launch_bounds__(128, 8):
// targets 64 regs/thread (live-state audit: ~55-60 worst case) so the
// regfile fits 8 blocks = 32 warps/SM instead of 24. The solver is
// latency-bound at issue=45.7% -- +33% warps attacks exactly that.
// ---------------------------------------------------------------------------

#define MAX_B 32768
#define CELLS 81
#define TPB   128        // 4 warps x 10 puzzles each
#define PPW   10         // puzzles per warp
#define PPB   (PPW * (TPB / 32))   // 40 puzzles per block

// Stack-local line index helpers: s[] holds 27 cells, s[r*3+c].
#define CIDX(l, k)  ((k) * 3 + (l))   // local column l, row k
#define BIDX(l, k)  ((l) * 9 + (k))   // local box l, cell k

#define UNIQUE3(IDX)                                                          \
    _Pragma("unroll")                                                         \
    for (int l = 0; l < 3; ++l) {                                             \
        unsigned ones = 0, more = 0;                                          \
        _Pragma("unroll")                                                     \
        for (int k = 0; k < 9; ++k) {                                         \
            unsigned x = s[IDX(l, k)];                                        \
            more |= ones & x;                                                 \
            ones ^= x;                                                        \
        }                                                                     \
        unsigned e1 = ones & ~more;                                           \
        _Pragma("unroll")                                                     \
        for (int k = 0; k < 9; ++k) {                                         \
            unsigned v = s[IDX(l, k)];                                        \
            unsigned h = v & e1;                                              \
            s[IDX(l, k)] = h ? h : v;                                         \
        }                                                                     \
    }

#define DOUBLES3(IDX)                                                         \
    _Pragma("unroll")                                                         \
    for (int l = 0; l < 3; ++l) {                                             \
        unsigned v[9], qm[9];                                                 \
        _Pragma("unroll")                                                     \
        for (int k = 0; k < 9; ++k) {                                         \
            v[k]  = s[IDX(l, k)];                                             \
            qm[k] = (__popc(v[k]) == 2) ? v[k] : (0x400u << k);               \
        }                                                                     \
        unsigned flag = 0, pd = 0;                                            \
        _Pragma("unroll")                                                     \
        for (int c = 0; c < 9; ++c) {                                         \
            _Pragma("unroll")                                                 \
            for (int e = c + 1; e < 9; ++e) {                                 \
                if (qm[c] == qm[e]) {                                         \
                    flag |= (1u << c) | (1u << e);                            \
                    pd   |= qm[c];                                            \
                }                                                             \
            }                                                                 \
        }                                                                     \
        unsigned npd = ~pd;                                                   \
        _Pragma("unroll")                                                     \
        for (int k = 0; k < 9; ++k) {                                         \
            s[IDX(l, k)] = ((flag >> k) & 1u) ? v[k] : (v[k] & npd);          \
        }                                                                     \
    }

__global__ void __launch_bounds__(TPB, 8)
fused_kernel(const float* __restrict__ in, float* __restrict__ out,
             float* __restrict__ out_tail, int B, int tail_mode)
{
    __shared__ unsigned sm[PPB * CELLS];          // 12.96 KB, per-warp segments

    const int tid      = threadIdx.x;
    const int lane     = tid & 31;
    const int w        = tid >> 5;
    const int warpBase = blockIdx.x * PPB + w * PPW;   // first puzzle of warp
    int nW = B - warpBase;
    if (nW > PPW) nW = PPW;
    if (nW < 0)   nW = 0;
    unsigned* seg = sm + w * (PPW * CELLS);

    // ================= pack (warp-private, division-free) =================
    for (int p = 0; p < nW; ++p) {
        const float* q = in + (size_t)(warpBase + p) * 729;
#pragma unroll
        for (int it = 0; it < 3; ++it) {
            int cell = lane + 32 * it;
            if (cell < CELLS) {
                unsigned mm = 0;
#pragma unroll
                for (int d = 0; d < 9; ++d)
                    mm |= (__ldcs(q + d * 81 + cell) != 0.0f) ? (1u << d) : 0u;
                seg[p * CELLS + cell] = mm;
            }
        }
    }
    __syncwarp();

    // ================= solve (3 lanes per puzzle, lanes 0..29) =============
    if (lane < 30) {
        const unsigned MASK = 0x3FFFFFFFu;
        const int grp  = lane / 3;                 // 0..9 = local puzzle
        const int t    = lane - 3 * grp;           // stack member 0..2
        const int b    = warpBase + grp;
        const bool valid = (grp < nW);
        const int lb   = lane - t;
        const int pl1  = lb + ((t + 1) % 3);
        const int pl2  = lb + ((t + 2) % 3);

        unsigned s[27];
#pragma unroll
        for (int r = 0; r < 9; ++r)
#pragma unroll
            for (int c = 0; c < 3; ++c)
                s[r * 3 + c] = seg[grp * CELLS + r * 9 + 3 * t + c];

#pragma unroll 1
        for (int pass = 0; pass < 4; ++pass) {

            // ---- 1. filter box (3 local boxes)
#pragma unroll
            for (int br = 0; br < 3; ++br) {
                unsigned sv[9], seen = 0, seen2 = 0;
#pragma unroll
                for (int k = 0; k < 9; ++k) {
                    unsigned vv = s[9 * br + k];
                    unsigned so = (__popc(vv) == 1) ? vv : 0u;
                    sv[k] = so;
                    seen2 |= seen & so;
                    seen  |= so;
                }
#pragma unroll
                for (int k = 0; k < 9; ++k) {
                    unsigned other = (seen & ~sv[k]) | (seen2 & sv[k]);
                    s[9 * br + k] &= ~other;
                }
            }

            // ---- 2. pointing h (cross-stack via SHFL)
            {
                unsigned ppk[3];
#pragma unroll
                for (int br = 0; br < 3; ++br) {
                    unsigned p0 = s[9*br+0] | s[9*br+1] | s[9*br+2];
                    unsigned p1 = s[9*br+3] | s[9*br+4] | s[9*br+5];
                    unsigned p2 = s[9*br+6] | s[9*br+7] | s[9*br+8];
                    unsigned maj = (p0 & p1) | ((p0 ^ p1) & p2);
                    unsigned e1  = (p0 ^ p1 ^ p2) & ~maj;
                    ppk[br] = (p0 & e1) | ((p1 & e1) << 9) | ((p2 & e1) << 18);
                }
#pragma unroll
                for (int br = 0; br < 3; ++br) {
                    unsigned rem = __shfl_sync(MASK, ppk[br], pl1)
                                 | __shfl_sync(MASK, ppk[br], pl2);
#pragma unroll
                    for (int ri = 0; ri < 3; ++ri) {
                        unsigned keep = ~((rem >> (9 * ri)) & 0x1FFu);
                        s[9*br+3*ri+0] &= keep;
                        s[9*br+3*ri+1] &= keep;
                        s[9*br+3*ri+2] &= keep;
                    }
                }
            }

            // ---- 3. pointing v (stack-local)
            {
                unsigned pt[3][3];
#pragma unroll
                for (int br = 0; br < 3; ++br) {
                    unsigned q0 = s[9*br+0] | s[9*br+3] | s[9*br+6];
                    unsigned q1 = s[9*br+1] | s[9*br+4] | s[9*br+7];
                    unsigned q2 = s[9*br+2] | s[9*br+5] | s[9*br+8];
                    unsigned maj = (q0 & q1) | ((q0 ^ q1) & q2);
                    unsigned e1  = (q0 ^ q1 ^ q2) & ~maj;
                    pt[br][0] = q0 & e1;  pt[br][1] = q1 & e1;  pt[br][2] = q2 & e1;
                }
#pragma unroll
                for (int br = 0; br < 3; ++br)
#pragma unroll
                    for (int ci = 0; ci < 3; ++ci) {
                        unsigned keep = ~(pt[(br+1)%3][ci] | pt[(br+2)%3][ci]);
                        s[9*br+ci]   &= keep;
                        s[9*br+3+ci] &= keep;
                        s[9*br+6+ci] &= keep;
                    }
            }

            // ---- 4. unique h (rows, cross-stack, packed CSA partials)
#pragma unroll
            for (int q = 0; q < 3; ++q) {
                unsigned opk = 0, mpk = 0;
#pragma unroll
                for (int j = 0; j < 3; ++j) {
                    int r = 3 * q + j;
                    unsigned x0 = s[3*r], x1 = s[3*r+1], x2 = s[3*r+2];
                    unsigned o  = x0 ^ x1 ^ x2;
                    unsigned mm = (x0 & x1) | ((x0 ^ x1) & x2);
                    opk |= o  << (9 * j);
                    mpk |= mm << (9 * j);
                }
                unsigned o1 = __shfl_sync(MASK, opk, pl1);
                unsigned o2 = __shfl_sync(MASK, opk, pl2);
                unsigned m1 = __shfl_sync(MASK, mpk, pl1);
                unsigned m2 = __shfl_sync(MASK, mpk, pl2);
                unsigned ones = opk ^ o1 ^ o2;
                unsigned more = mpk | m1 | m2 | (opk & o1) | ((opk ^ o1) & o2);
                unsigned e1p  = ones & ~more;
#pragma unroll
                for (int j = 0; j < 3; ++j) {
                    int r = 3 * q + j;
                    unsigned e1 = (e1p >> (9 * j)) & 0x1FFu;
#pragma unroll
                    for (int c = 0; c < 3; ++c) {
                        unsigned v = s[3*r+c];
                        unsigned h = v & e1;
                        s[3*r+c] = h ? h : v;
                    }
                }
            }

            // ---- 5/6. unique v (local cols), unique box (local)
            UNIQUE3(CIDX)
            UNIQUE3(BIDX)

            // ---- 7/8/9. naked pairs: col, col, box
            DOUBLES3(CIDX)
            DOUBLES3(CIDX)
            DOUBLES3(BIDX)
        }

        // solved flag across the 3 stacks
        unsigned svf = 1;
#pragma unroll
        for (int i = 0; i < 27; ++i)
            svf &= (unsigned)(__popc(s[i]) == 1);
        unsigned sv1 = __shfl_sync(MASK, svf, pl1);
        unsigned sv2 = __shfl_sync(MASK, svf, pl2);
        unsigned solved = svf & sv1 & sv2;

        if (valid) {
#pragma unroll
            for (int r = 0; r < 9; ++r)
#pragma unroll
                for (int c = 0; c < 3; ++c)
                    seg[grp * CELLS + r * 9 + 3 * t + c] = s[r * 3 + c];

            if (t == 0) {
                if (tail_mode == 1) {
                    out_tail[b] = solved ? 1.0f : 0.0f;
                } else if (tail_mode == 2) {
                    ((unsigned char*)out_tail)[b] = solved ? 1 : 0;
                }
            }
        }
    }
    __syncwarp();

    // ================= unpack (warp-private, division-free) ================
    for (int p = 0; p < nW; ++p) {
        float* q = out + (size_t)(warpBase + p) * 729;
#pragma unroll
        for (int it = 0; it < 3; ++it) {
            int cell = lane + 32 * it;
            if (cell < CELLS) {
                unsigned mm = seg[p * CELLS + cell];
#pragma unroll
                for (int d = 0; d < 9; ++d)
                    __stcs(q + d * 81 + cell,
                           __uint_as_float(((mm >> d) & 1u) * 0x3F800000u));
            }
        }
    }
}

// ---------------------------------------------------------------------------
extern "C" void kernel_launch(void* const* d_in, const int* in_sizes, int n_in,
                              void* d_out, int out_size)
{
    const float* in = (const float*)d_in[0];
    float* out = (float*)d_out;

    int B = in_sizes[0] / 729;
    if (B > MAX_B) B = MAX_B;

    int tail_mode = 0;
    float* tail_ptr = out + (size_t)B * 729;
    if (out_size >= B * 729 + B) {
        tail_mode = 1;                                   // float-encoded bools
    } else if (out_size >= B * 729 + (B + 3) / 4) {
        tail_mode = 2;                                   // raw bool bytes
    }

    int blocks = (B + PPB - 1) / PPB;   // 820 for B=32768
    fused_kernel<<<blocks, TPB>>>(in, out, tail_ptr, B, tail_mode);
}

// round 17
// speedup vs baseline: 1.8402x; 1.0004x over previous
#include <cuda_runtime.h>
#include <cuda_bf16.h>
#include <cstdint>

// ---------------------------------------------------------------------------
// SudokuPasses: 4 passes of {filter(box), pointing(h), pointing(v),
// unique(h), unique(v), unique(box), doubles(v), doubles(v), doubles(box)}
// over B=32768 puzzles of (9 digits, 9 rows, 9 cols) {0,1} float masks.
//
// R16 == R15 resubmitted (previous round died to a container-broker infra
// failure before compile/run). TPB=64 (2 warps/block, PPB=20): grid 1639
// blocks; at 64 regs the regfile fits 16 blocks/SM = 32 warps (R14 was
// grid-capped at ~5.5 blocks = 22 warps avg with a coarse tail). Solver
// idles ~35% of issue slots (issue=45%, alu 66% of peak); more resident
// warps is the direct fix. Solver body unchanged.
// ---------------------------------------------------------------------------

#define MAX_B 32768
#define CELLS 81
#define TPB   64         // 2 warps x 10 puzzles each
#define PPW   10         // puzzles per warp
#define PPB   (PPW * (TPB / 32))   // 20 puzzles per block

// Stack-local line index helpers: s[] holds 27 cells, s[r*3+c].
#define CIDX(l, k)  ((k) * 3 + (l))   // local column l, row k
#define BIDX(l, k)  ((l) * 9 + (k))   // local box l, cell k

#define UNIQUE3(IDX)                                                          \
    _Pragma("unroll")                                                         \
    for (int l = 0; l < 3; ++l) {                                             \
        unsigned ones = 0, more = 0;                                          \
        _Pragma("unroll")                                                     \
        for (int k = 0; k < 9; ++k) {                                         \
            unsigned x = s[IDX(l, k)];                                        \
            more |= ones & x;                                                 \
            ones ^= x;                                                        \
        }                                                                     \
        unsigned e1 = ones & ~more;                                           \
        _Pragma("unroll")                                                     \
        for (int k = 0; k < 9; ++k) {                                         \
            unsigned v = s[IDX(l, k)];                                        \
            unsigned h = v & e1;                                              \
            s[IDX(l, k)] = h ? h : v;                                         \
        }                                                                     \
    }

#define DOUBLES3(IDX)                                                         \
    _Pragma("unroll")                                                         \
    for (int l = 0; l < 3; ++l) {                                             \
        unsigned v[9], qm[9];                                                 \
        _Pragma("unroll")                                                     \
        for (int k = 0; k < 9; ++k) {                                         \
            v[k]  = s[IDX(l, k)];                                             \
            qm[k] = (__popc(v[k]) == 2) ? v[k] : (0x400u << k);               \
        }                                                                     \
        unsigned flag = 0, pd = 0;                                            \
        _Pragma("unroll")                                                     \
        for (int c = 0; c < 9; ++c) {                                         \
            _Pragma("unroll")                                                 \
            for (int e = c + 1; e < 9; ++e) {                                 \
                if (qm[c] == qm[e]) {                                         \
                    flag |= (1u << c) | (1u << e);                            \
                    pd   |= qm[c];                                            \
                }                                                             \
            }                                                                 \
        }                                                                     \
        unsigned npd = ~pd;                                                   \
        _Pragma("unroll")                                                     \
        for (int k = 0; k < 9; ++k) {                                         \
            s[IDX(l, k)] = ((flag >> k) & 1u) ? v[k] : (v[k] & npd);          \
        }                                                                     \
    }

__global__ void __launch_bounds__(TPB, 16)
fused_kernel(const float* __restrict__ in, float* __restrict__ out,
             float* __restrict__ out_tail, int B, int tail_mode)
{
    __shared__ unsigned sm[PPB * CELLS];          // 6.48 KB, per-warp segments

    const int tid      = threadIdx.x;
    const int lane     = tid & 31;
    const int w        = tid >> 5;
    const int warpBase = blockIdx.x * PPB + w * PPW;   // first puzzle of warp
    int nW = B - warpBase;
    if (nW > PPW) nW = PPW;
    if (nW < 0)   nW = 0;
    unsigned* seg = sm + w * (PPW * CELLS);

    // ================= pack (warp-private, division-free) =================
    for (int p = 0; p < nW; ++p) {
        const float* q = in + (size_t)(warpBase + p) * 729;
#pragma unroll
        for (int it = 0; it < 3; ++it) {
            int cell = lane + 32 * it;
            if (cell < CELLS) {
                unsigned mm = 0;
#pragma unroll
                for (int d = 0; d < 9; ++d)
                    mm |= (__ldcs(q + d * 81 + cell) != 0.0f) ? (1u << d) : 0u;
                seg[p * CELLS + cell] = mm;
            }
        }
    }
    __syncwarp();

    // ================= solve (3 lanes per puzzle, lanes 0..29) =============
    if (lane < 30) {
        const unsigned MASK = 0x3FFFFFFFu;
        const int grp  = lane / 3;                 // 0..9 = local puzzle
        const int t    = lane - 3 * grp;           // stack member 0..2
        const int b    = warpBase + grp;
        const bool valid = (grp < nW);
        const int lb   = lane - t;
        const int pl1  = lb + ((t + 1) % 3);
        const int pl2  = lb + ((t + 2) % 3);

        unsigned s[27];
#pragma unroll
        for (int r = 0; r < 9; ++r)
#pragma unroll
            for (int c = 0; c < 3; ++c)
                s[r * 3 + c] = seg[grp * CELLS + r * 9 + 3 * t + c];

#pragma unroll 1
        for (int pass = 0; pass < 4; ++pass) {

            // ---- 1. filter box (3 local boxes)
#pragma unroll
            for (int br = 0; br < 3; ++br) {
                unsigned sv[9], seen = 0, seen2 = 0;
#pragma unroll
                for (int k = 0; k < 9; ++k) {
                    unsigned vv = s[9 * br + k];
                    unsigned so = (__popc(vv) == 1) ? vv : 0u;
                    sv[k] = so;
                    seen2 |= seen & so;
                    seen  |= so;
                }
#pragma unroll
                for (int k = 0; k < 9; ++k) {
                    unsigned other = (seen & ~sv[k]) | (seen2 & sv[k]);
                    s[9 * br + k] &= ~other;
                }
            }

            // ---- 2. pointing h (cross-stack via SHFL)
            {
                unsigned ppk[3];
#pragma unroll
                for (int br = 0; br < 3; ++br) {
                    unsigned p0 = s[9*br+0] | s[9*br+1] | s[9*br+2];
                    unsigned p1 = s[9*br+3] | s[9*br+4] | s[9*br+5];
                    unsigned p2 = s[9*br+6] | s[9*br+7] | s[9*br+8];
                    unsigned maj = (p0 & p1) | ((p0 ^ p1) & p2);
                    unsigned e1  = (p0 ^ p1 ^ p2) & ~maj;
                    ppk[br] = (p0 & e1) | ((p1 & e1) << 9) | ((p2 & e1) << 18);
                }
#pragma unroll
                for (int br = 0; br < 3; ++br) {
                    unsigned rem = __shfl_sync(MASK, ppk[br], pl1)
                                 | __shfl_sync(MASK, ppk[br], pl2);
#pragma unroll
                    for (int ri = 0; ri < 3; ++ri) {
                        unsigned keep = ~((rem >> (9 * ri)) & 0x1FFu);
                        s[9*br+3*ri+0] &= keep;
                        s[9*br+3*ri+1] &= keep;
                        s[9*br+3*ri+2] &= keep;
                    }
                }
            }

            // ---- 3. pointing v (stack-local)
            {
                unsigned pt[3][3];
#pragma unroll
                for (int br = 0; br < 3; ++br) {
                    unsigned q0 = s[9*br+0] | s[9*br+3] | s[9*br+6];
                    unsigned q1 = s[9*br+1] | s[9*br+4] | s[9*br+7];
                    unsigned q2 = s[9*br+2] | s[9*br+5] | s[9*br+8];
                    unsigned maj = (q0 & q1) | ((q0 ^ q1) & q2);
                    unsigned e1  = (q0 ^ q1 ^ q2) & ~maj;
                    pt[br][0] = q0 & e1;  pt[br][1] = q1 & e1;  pt[br][2] = q2 & e1;
                }
#pragma unroll
                for (int br = 0; br < 3; ++br)
#pragma unroll
                    for (int ci = 0; ci < 3; ++ci) {
                        unsigned keep = ~(pt[(br+1)%3][ci] | pt[(br+2)%3][ci]);
                        s[9*br+ci]   &= keep;
                        s[9*br+3+ci] &= keep;
                        s[9*br+6+ci] &= keep;
                    }
            }

            // ---- 4. unique h (rows, cross-stack, packed CSA partials)
#pragma unroll
            for (int q = 0; q < 3; ++q) {
                unsigned opk = 0, mpk = 0;
#pragma unroll
                for (int j = 0; j < 3; ++j) {
                    int r = 3 * q + j;
                    unsigned x0 = s[3*r], x1 = s[3*r+1], x2 = s[3*r+2];
                    unsigned o  = x0 ^ x1 ^ x2;
                    unsigned mm = (x0 & x1) | ((x0 ^ x1) & x2);
                    opk |= o  << (9 * j);
                    mpk |= mm << (9 * j);
                }
                unsigned o1 = __shfl_sync(MASK, opk, pl1);
                unsigned o2 = __shfl_sync(MASK, opk, pl2);
                unsigned m1 = __shfl_sync(MASK, mpk, pl1);
                unsigned m2 = __shfl_sync(MASK, mpk, pl2);
                unsigned ones = opk ^ o1 ^ o2;
                unsigned more = mpk | m1 | m2 | (opk & o1) | ((opk ^ o1) & o2);
                unsigned e1p  = ones & ~more;
#pragma unroll
                for (int j = 0; j < 3; ++j) {
                    int r = 3 * q + j;
                    unsigned e1 = (e1p >> (9 * j)) & 0x1FFu;
#pragma unroll
                    for (int c = 0; c < 3; ++c) {
                        unsigned v = s[3*r+c];
                        unsigned h = v & e1;
                        s[3*r+c] = h ? h : v;
                    }
                }
            }

            // ---- 5/6. unique v (local cols), unique box (local)
            UNIQUE3(CIDX)
            UNIQUE3(BIDX)

            // ---- 7/8/9. naked pairs: col, col, box
            DOUBLES3(CIDX)
            DOUBLES3(CIDX)
            DOUBLES3(BIDX)
        }

        // solved flag across the 3 stacks
        unsigned svf = 1;
#pragma unroll
        for (int i = 0; i < 27; ++i)
            svf &= (unsigned)(__popc(s[i]) == 1);
        unsigned sv1 = __shfl_sync(MASK, svf, pl1);
        unsigned sv2 = __shfl_sync(MASK, svf, pl2);
        unsigned solved = svf & sv1 & sv2;

        if (valid) {
#pragma unroll
            for (int r = 0; r < 9; ++r)
#pragma unroll
                for (int c = 0; c < 3; ++c)
                    seg[grp * CELLS + r * 9 + 3 * t + c] = s[r * 3 + c];

            if (t == 0) {
                if (tail_mode == 1) {
                    out_tail[b] = solved ? 1.0f : 0.0f;
                } else if (tail_mode == 2) {
                    ((unsigned char*)out_tail)[b] = solved ? 1 : 0;
                }
            }
        }
    }
    __syncwarp();

    // ================= unpack (warp-private, division-free) ================
    for (int p = 0; p < nW; ++p) {
        float* q = out + (size_t)(warpBase + p) * 729;
#pragma unroll
        for (int it = 0; it < 3; ++it) {
            int cell = lane + 32 * it;
            if (cell < CELLS) {
                unsigned mm = seg[p * CELLS + cell];
#pragma unroll
                for (int d = 0; d < 9; ++d)
                    __stcs(q + d * 81 + cell,
                           __uint_as_float(((mm >> d) & 1u) * 0x3F800000u));
            }
        }
    }
}

// ---------------------------------------------------------------------------
extern "C" void kernel_launch(void* const* d_in, const int* in_sizes, int n_in,
                              void* d_out, int out_size)
{
    const float* in = (const float*)d_in[0];
    float* out = (float*)d_out;

    int B = in_sizes[0] / 729;
    if (B > MAX_B) B = MAX_B;

    int tail_mode = 0;
    float* tail_ptr = out + (size_t)B * 729;
    if (out_size >= B * 729 + B) {
        tail_mode = 1;                                   // float-encoded bools
    } else if (out_size >= B * 729 + (B + 3) / 4) {
        tail_mode = 2;                                   // raw bool bytes
    }

    int blocks = (B + PPB - 1) / PPB;   // 1639 for B=32768
    fused_kernel<<<blocks, TPB>>>(in, out, tail_ptr, B, tail_mode);
}